// round 12
// baseline (speedup 1.0000x reference)
#include <cuda_runtime.h>

// B=2, C=8, img (n,256,256) -> out (n,1024,1024). CDF2.3 23-tap, 2 stages,
// fully fused: per block one 64x128 output tile computed end-to-end.
// Weight sparsity: odd taps zero except w[11]; 12 even taps dense (values
// loaded from the real weight input).
#define CH    8
#define NB    16
#define KTAPS 23

typedef unsigned long long u64;
__device__ __forceinline__ u64 pack2(float lo, float hi) {
    u64 d; asm("mov.b64 %0, {%1, %2};" : "=l"(d) : "f"(lo), "f"(hi)); return d;
}
__device__ __forceinline__ u64 fma2(u64 a, u64 b, u64 c) {
    u64 d; asm("fma.rn.f32x2 %0, %1, %2, %3;" : "=l"(d) : "l"(a), "l"(b), "l"(c)); return d;
}
__device__ __forceinline__ u64 mul2(u64 a, u64 b) {
    u64 d; asm("mul.rn.f32x2 %0, %1, %2;" : "=l"(d) : "l"(a), "l"(b)); return d;
}

// Tile geometry: out tile 64 rows x 128 cols at (y0, x0); grid (8,16,16).
//  t0  = y0/2 - 5          (s1 row base, odd)        s1 tile: 43 x 80
//  cb1 = x0/2 - 8          (s1 col base, even)
//  t0h = 16*by - 8         (s1h/img row base)        s1h tile: 32 x 80
//  ci0 = 32*bx - 10        (img col base)            img tile: 32 x 51 (pad 56)
// Phase formulas (derived from the verified R4 polyphase kernels):
//  P2 s1h: col 2m   = sum_t img[m+t]*we[t] ; col 2m+1 = img[m+6]*w11
//  P3 s1 : row jj even = sh1[jj/2+5]*w11  ; jj odd = sum_t sh1[(jj-1)/2+t]*we[t]
//  P4 s2h: col ll even = ss1[ll/2+8]*w11  ; ll odd = sum_t ss1[(ll-1)/2+3+t]*we[t]
//  P5 out: row 2a = sh2[a+5]*w11          ; row 2a+1 = sum_t sh2[a+t]*we[t]
__global__ void __launch_bounds__(256) fused(const float* __restrict__ in,
                                             float* __restrict__ out,
                                             const float* __restrict__ wt)
{
    __shared__ float s_ss1[43 * 80];     // s1 tile (rows 43, stride 80)
    __shared__ float s_B[5504];          // union: {simg[32][56] + sh1[32][80]} then sh2[43][128]
    float* const simg = s_B;             // 32 x 56  (1792)
    float* const sh1  = s_B + 1792;      // 32 x 80  (2560)
    float* const sh2  = s_B;             // 43 x 128 (5504) — overwrites simg/sh1 after P3

    const int n = blockIdx.z;
    const float* wb = wt + (n & (CH - 1)) * KTAPS;
    float we[12];
#pragma unroll
    for (int t = 0; t < 12; t++) we[t] = __ldg(&wb[2 * t]);
    const float w11 = __ldg(&wb[11]);

    const int bx = blockIdx.x, by = blockIdx.y;
    const int x0 = bx * 128, y0 = by * 64;
    const int t0h = 16 * by - 8;
    const int ci0 = 32 * bx - 10;
    const int tid = threadIdx.x;

    const float* __restrict__ ibase = in + (size_t)n * 256 * 256;

    // ---- P1: load img tile simg[32][56] (cols used: 0..50), circular ----
    if (ci0 >= 0 && ci0 + 55 < 256) {
        for (int idx = tid; idx < 32 * 28; idx += 256) {
            const int rr = idx / 28, c2 = idx - rr * 28;
            const int gr = (t0h + rr + 256) & 255;
            *(float2*)&simg[rr * 56 + 2 * c2] =
                *(const float2*)(ibase + (size_t)gr * 256 + ci0 + 2 * c2);
        }
    } else {
        for (int idx = tid; idx < 32 * 56; idx += 256) {
            const int rr = idx / 56, cc = idx - rr * 56;
            const int gr = (t0h + rr + 256) & 255;
            const int gc = (ci0 + cc + 256) & 255;
            simg[rr * 56 + cc] = ibase[(size_t)gr * 256 + gc];
        }
    }
    __syncthreads();

    // ---- P2: s1h tile sh1[32][80]; jobs: 32 rows x 10 (4-m groups) ----
    for (int job = tid; job < 32 * 10; job += 256) {
        const int rr = job / 10, g = job - rr * 10;
        const int m0 = 4 * g;
        float v[20];
#pragma unroll
        for (int q = 0; q < 5; q++) {
            float4 f = *(const float4*)&simg[rr * 56 + m0 + 4 * q];
            v[4*q] = f.x; v[4*q+1] = f.y; v[4*q+2] = f.z; v[4*q+3] = f.w;
        }
        float o8[8];
#pragma unroll
        for (int i = 0; i < 4; i++) {
            float cv = 0.f;
#pragma unroll
            for (int t = 0; t < 12; t++) cv = fmaf(v[i + t], we[t], cv);
            o8[2*i]   = cv;                // s1h col 2(m0+i)
            o8[2*i+1] = v[i + 6] * w11;    // s1h col 2(m0+i)+1
        }
        *(float4*)&sh1[rr * 80 + 8 * g]     = make_float4(o8[0], o8[1], o8[2], o8[3]);
        *(float4*)&sh1[rr * 80 + 8 * g + 4] = make_float4(o8[4], o8[5], o8[6], o8[7]);
    }
    __syncthreads();

    // ---- P3: s1 tile ss1[43][80]; jobs: 43 rows x 20 (4-col groups) ----
    for (int job = tid; job < 43 * 20; job += 256) {
        const int jj = job / 20, k = job - jj * 20;
        const int c4 = 4 * k;
        float4 r;
        if ((jj & 1) == 0) {               // copy row
            float4 f = *(const float4*)&sh1[(jj / 2 + 5) * 80 + c4];
            r = make_float4(f.x * w11, f.y * w11, f.z * w11, f.w * w11);
        } else {                           // conv row
            const int rb = (jj - 1) >> 1;
            float ax = 0.f, ay = 0.f, az = 0.f, aw = 0.f;
#pragma unroll
            for (int t = 0; t < 12; t++) {
                float4 f = *(const float4*)&sh1[(rb + t) * 80 + c4];
                ax = fmaf(f.x, we[t], ax); ay = fmaf(f.y, we[t], ay);
                az = fmaf(f.z, we[t], az); aw = fmaf(f.w, we[t], aw);
            }
            r = make_float4(ax, ay, az, aw);
        }
        *(float4*)&s_ss1[jj * 80 + c4] = r;
    }
    __syncthreads();

    // ---- P4: s2h tile sh2[43][128]; jobs: 43 rows x 16 (8-col groups) ----
    // (sh2 overwrites simg/sh1 — both dead after P3.)
    for (int job = tid; job < 43 * 16; job += 256) {
        const int rr = job / 16, g = job - rr * 16;
        const int u0 = 4 * g;              // ss1 local col base; window [u0, u0+19]
        float u[20];
#pragma unroll
        for (int q = 0; q < 5; q++) {
            float4 f = *(const float4*)&s_ss1[rr * 80 + u0 + 4 * q];
            u[4*q] = f.x; u[4*q+1] = f.y; u[4*q+2] = f.z; u[4*q+3] = f.w;
        }
        float o8[8];
#pragma unroll
        for (int s = 0; s < 4; s++) {      // out col pairs (8g+2s, 8g+2s+1)
            o8[2*s] = u[s + 8] * w11;      // even col
            float cv = 0.f;
#pragma unroll
            for (int t = 0; t < 12; t++) cv = fmaf(u[s + 3 + t], we[t], cv);
            o8[2*s+1] = cv;                // odd col
        }
        *(float4*)&sh2[rr * 128 + 8 * g]     = make_float4(o8[0], o8[1], o8[2], o8[3]);
        *(float4*)&sh2[rr * 128 + 8 * g + 4] = make_float4(o8[4], o8[5], o8[6], o8[7]);
    }
    __syncthreads();

    // ---- P5: vertical polyphase -> out; thread = (col-pair p, quarter h) ----
    const int p = tid & 63;                // cols 2p, 2p+1 of the 128-wide tile
    const int h = tid >> 6;                // output rows 16h .. 16h+15
    u64 wp[12];
#pragma unroll
    for (int t = 0; t < 12; t++) wp[t] = pack2(we[t], we[t]);
    const u64 w11p = pack2(w11, w11);

    float* __restrict__ obase =
        out + ((size_t)n * 1024 + y0 + 16 * h) * 1024 + x0 + 2 * p;

    u64 win[12];
#pragma unroll
    for (int q = 0; q < 12; q++)
        win[q] = *(const u64*)&sh2[(8 * h + q) * 128 + 2 * p];

#pragma unroll
    for (int s = 0; s < 8; s++) {          // a = 8h+s; rows 2s (copy), 2s+1 (conv)
        u64 cv = mul2(win[0], wp[0]);
#pragma unroll
        for (int t = 1; t < 12; t++) cv = fma2(win[t], wp[t], cv);
        const u64 cpv = mul2(win[5], w11p);
        *(u64*)(obase + (size_t)(2 * s)     * 1024) = cpv;
        *(u64*)(obase + (size_t)(2 * s + 1) * 1024) = cv;
        if (s < 7) {
#pragma unroll
            for (int q = 0; q < 11; q++) win[q] = win[q + 1];
            win[11] = *(const u64*)&sh2[(8 * h + s + 12) * 128 + 2 * p];
        }
    }
}

extern "C" void kernel_launch(void* const* d_in, const int* in_sizes, int n_in,
                              void* d_out, int out_size)
{
    (void)in_sizes; (void)n_in; (void)out_size;
    const float* img = (const float*)d_in[0];   // (2,8,256,256)
    const float* wt  = (const float*)d_in[1];   // (8,23)
    float* out = (float*)d_out;                 // (2,8,1024,1024)

    fused<<<dim3(8, 16, NB), 256>>>(img, out, wt);
}

// round 13
// speedup vs baseline: 1.0088x; 1.0088x over previous
#include <cuda_runtime.h>

// B=2, C=8, 256x256 -> 1024x1024, CDF2.3 23-tap, two polyphase stages.
// Sparsity: odd taps all zero except w[11]; 12 even taps dense (values read
// from the real weight input each launch).
#define CH    8
#define NB    16
#define KTAPS 23

__device__ float g_s1[16ull * 512 * 512];   // stage-1 output (16MB)

typedef unsigned long long u64;
__device__ __forceinline__ u64 pack2(float lo, float hi) {
    u64 d; asm("mov.b64 %0, {%1, %2};" : "=l"(d) : "f"(lo), "f"(hi)); return d;
}
__device__ __forceinline__ u64 fma2(u64 a, u64 b, u64 c) {
    u64 d; asm("fma.rn.f32x2 %0, %1, %2, %3;" : "=l"(d) : "l"(a), "l"(b), "l"(c)); return d;
}
__device__ __forceinline__ u64 mul2(u64 a, u64 b) {
    u64 d; asm("mul.rn.f32x2 %0, %1, %2;" : "=l"(d) : "l"(a), "l"(b)); return d;
}
__device__ __forceinline__ u64 add2(u64 a, u64 b) {
    u64 d; asm("add.rn.f32x2 %0, %1, %2;" : "=l"(d) : "l"(a), "l"(b)); return d;
}

// ---------------------------------------------------------------------------
// Upsample stage: in (NB,H,W) -> out (NB,2H,2W), phase O.
// Out tile: RO rows x 256 cols; 256 threads; s_tmp[RO/2+11][256].
//  Phase H: 8-input-col jobs, 24-float window direct from global:
//   O=1: out col 2c = sum_t v[i+2+t]we[t], col 2c+1 = v[i+8]w11   (v from c0-8)
//   O=0: col 2c = v[i+8]w11, col 2c+1 = sum_t v[i+3+t]we[t]
//  Phase V: thread = (col-pair p, half h); RO/2 rows per thread, rolling
//   12-row packed window; step s: conv = sum win[t]wp[t], copy = win[5+O]w11.
//   O=0: row 2s = copy, 2s+1 = conv.  O=1: row 2s = conv, 2s+1 = copy.
// ---------------------------------------------------------------------------
template<int O, int H, int W, int RO>
__global__ void __launch_bounds__(256) fstage(const float* __restrict__ in,
                                              float* __restrict__ out,
                                              const float* __restrict__ wt)
{
    constexpr int NR = RO / 2 + 11;          // s_tmp rows
    __shared__ float s_tmp[NR][256];

    const int n = blockIdx.z;
    const float* wb = wt + (n & (CH - 1)) * KTAPS;
    float we[12];
#pragma unroll
    for (int t = 0; t < 12; t++) we[t] = __ldg(&wb[2 * t]);
    const float w11 = __ldg(&wb[11]);

    const int x0 = blockIdx.x * 256;         // output col base
    const int y0 = blockIdx.y * RO;          // output row base
    const int c0 = x0 >> 1;                  // input col base
    const int t0 = (y0 >> 1) - 5 - O;        // input row base (may be negative)
    const int tid = threadIdx.x;

    const float* __restrict__ ibase = in + (size_t)n * H * W;

    // ---- Phase H: NR rows x 16 eight-col jobs, direct from global ----
    for (int job = tid; job < NR * 16; job += 256) {
        const int rr = job >> 4, g8 = job & 15;
        const int gr = (t0 + rr + H) & (H - 1);
        const float* __restrict__ row = ibase + (size_t)gr * W;
        const int cb = c0 - 8 + 8 * g8;      // window = input cols [cb, cb+23]

        float v[24];
        if (cb >= 0 && cb + 24 <= W) {       // cb % 8 == 0 by construction
#pragma unroll
            for (int q = 0; q < 6; q++) {
                float4 f = *(const float4*)(row + cb + 4 * q);
                v[4*q] = f.x; v[4*q+1] = f.y; v[4*q+2] = f.z; v[4*q+3] = f.w;
            }
        } else {
#pragma unroll
            for (int q = 0; q < 24; q++)
                v[q] = row[(cb + q + W) & (W - 1)];
        }

        float o16[16];
#pragma unroll
        for (int i = 0; i < 8; i++) {
            float a0 = 0.f, a1 = 0.f;        // split chains (even/odd taps)
            if (O == 1) {
#pragma unroll
                for (int t = 0; t < 12; t += 2) {
                    a0 = fmaf(v[i + 2 + t], we[t], a0);
                    a1 = fmaf(v[i + 3 + t], we[t + 1], a1);
                }
                o16[2*i]   = a0 + a1;
                o16[2*i+1] = v[i + 8] * w11;
            } else {
#pragma unroll
                for (int t = 0; t < 12; t += 2) {
                    a0 = fmaf(v[i + 3 + t], we[t], a0);
                    a1 = fmaf(v[i + 4 + t], we[t + 1], a1);
                }
                o16[2*i]   = v[i + 8] * w11;
                o16[2*i+1] = a0 + a1;
            }
        }
#pragma unroll
        for (int q = 0; q < 4; q++)
            *(float4*)&s_tmp[rr][16 * g8 + 4 * q] =
                make_float4(o16[4*q], o16[4*q+1], o16[4*q+2], o16[4*q+3]);
    }
    __syncthreads();

    // ---- Phase V: packed rolling-window vertical polyphase ----
    const int p = tid & 127;                 // cols 2p, 2p+1
    const int h = tid >> 7;                  // half: output rows (RO/2)*h ..
    constexpr int S = RO / 4;                // steps per half
    const int qb = S * h;                    // s_tmp row base

    u64 wp[12];
#pragma unroll
    for (int t = 0; t < 12; t++) wp[t] = pack2(we[t], we[t]);
    const u64 w11p = pack2(w11, w11);

    float* __restrict__ obase =
        out + ((size_t)n * 2 * H + y0 + (RO / 2) * h) * (2 * W) + x0 + 2 * p;

    u64 win[12];
#pragma unroll
    for (int q = 0; q < 12; q++)
        win[q] = *(const u64*)&s_tmp[qb + q][2 * p];

#pragma unroll
    for (int s = 0; s < S; s++) {
        u64 c0a = mul2(win[0], wp[0]);
        u64 c1a = mul2(win[1], wp[1]);
#pragma unroll
        for (int t = 2; t < 12; t += 2) {
            c0a = fma2(win[t],     wp[t],     c0a);
            c1a = fma2(win[t + 1], wp[t + 1], c1a);
        }
        const u64 cv  = add2(c0a, c1a);
        const u64 cpv = mul2(win[5 + O], w11p);
        if (O == 0) {
            *(u64*)(obase + (size_t)(2 * s)     * (2 * W)) = cpv;
            *(u64*)(obase + (size_t)(2 * s + 1) * (2 * W)) = cv;
        } else {
            *(u64*)(obase + (size_t)(2 * s)     * (2 * W)) = cv;
            *(u64*)(obase + (size_t)(2 * s + 1) * (2 * W)) = cpv;
        }
        if (s < S - 1) {
#pragma unroll
            for (int q = 0; q < 11; q++) win[q] = win[q + 1];
            win[11] = *(const u64*)&s_tmp[qb + s + 12][2 * p];
        }
    }
}

extern "C" void kernel_launch(void* const* d_in, const int* in_sizes, int n_in,
                              void* d_out, int out_size)
{
    (void)in_sizes; (void)n_in; (void)out_size;
    const float* img = (const float*)d_in[0];   // (2,8,256,256)
    const float* wt  = (const float*)d_in[1];   // (8,23)
    float* out = (float*)d_out;                 // (2,8,1024,1024)

    float* s1;
    cudaGetSymbolAddress((void**)&s1, g_s1);

    // Stage 1 (O=1): 256x256 -> 512x512; 32x256 tiles -> grid (2,16,16).
    fstage<1, 256, 256, 32><<<dim3(2, 16, NB), 256>>>(img, s1, wt);

    // Stage 2 (O=0): 512x512 -> 1024x1024; 64x256 tiles -> grid (4,16,16).
    fstage<0, 512, 512, 64><<<dim3(4, 16, NB), 256>>>(s1, out, wt);
}